// round 1
// baseline (speedup 1.0000x reference)
#include <cuda_runtime.h>
#include <math.h>

#define B_  4
#define S_  2048
#define HID 1024
#define NH  16
#define HD  64

// Scratch for projected Q/K/V in [B, H, S, D] layout (static device globals:
// allocation inside kernel_launch is forbidden).
__device__ float g_Q[B_ * NH * S_ * HD];
__device__ float g_K[B_ * NH * S_ * HD];
__device__ float g_V[B_ * NH * S_ * HD];

// ---------------------------------------------------------------------------
// Kernel 1: y = x @ W + b for W in {Wq, Wk, Wv} (blockIdx.z selects),
// scattered into [B, H, S, D].
// 64x64 block tile, 16-wide k panel, 256 threads, 4x4 microtile per thread.
// ---------------------------------------------------------------------------
__global__ __launch_bounds__(256) void qkv_gemm(
    const float* __restrict__ x,
    const float* __restrict__ Wq, const float* __restrict__ bq,
    const float* __restrict__ Wk, const float* __restrict__ bk,
    const float* __restrict__ Wv, const float* __restrict__ bv)
{
    const float* W;
    const float* bias;
    float* dst;
    if (blockIdx.z == 0)      { W = Wq; bias = bq; dst = g_Q; }
    else if (blockIdx.z == 1) { W = Wk; bias = bk; dst = g_K; }
    else                      { W = Wv; bias = bv; dst = g_V; }

    __shared__ float As[16][68];   // [k][m], padded for float4 + banks
    __shared__ float Bs[16][68];   // [k][n]

    const int m0  = blockIdx.y * 64;
    const int n0  = blockIdx.x * 64;
    const int tid = threadIdx.x;
    const int tx  = tid & 15;      // n microtile
    const int ty  = tid >> 4;      // m microtile

    float acc[4][4] = {};

    for (int k0 = 0; k0 < HID; k0 += 16) {
        #pragma unroll
        for (int i = 0; i < 4; i++) {
            int idx = tid + i * 256;          // 0..1023
            int mm  = idx >> 4;
            int kk  = idx & 15;
            As[kk][mm] = x[(m0 + mm) * HID + (k0 + kk)];
        }
        #pragma unroll
        for (int i = 0; i < 4; i++) {
            int idx = tid + i * 256;
            int kk  = idx >> 6;
            int nn  = idx & 63;
            Bs[kk][nn] = W[(k0 + kk) * HID + (n0 + nn)];
        }
        __syncthreads();

        #pragma unroll
        for (int kk = 0; kk < 16; kk++) {
            float4 a = *reinterpret_cast<const float4*>(&As[kk][ty * 4]);
            float4 w = *reinterpret_cast<const float4*>(&Bs[kk][tx * 4]);
            float av[4] = {a.x, a.y, a.z, a.w};
            float wv[4] = {w.x, w.y, w.z, w.w};
            #pragma unroll
            for (int i = 0; i < 4; i++)
                #pragma unroll
                for (int j = 0; j < 4; j++)
                    acc[i][j] += av[i] * wv[j];
        }
        __syncthreads();
    }

    // One 64-wide n-tile == exactly one head.
    const int h = n0 >> 6;
    #pragma unroll
    for (int i = 0; i < 4; i++) {
        int m = m0 + ty * 4 + i;
        int b = m >> 11;            // / S_
        int s = m & (S_ - 1);
        #pragma unroll
        for (int j = 0; j < 4; j++) {
            int n = n0 + tx * 4 + j;
            int d = n & 63;
            dst[(((size_t)b * NH + h) * S_ + s) * HD + d] = acc[i][j] + bias[n];
        }
    }
}

// ---------------------------------------------------------------------------
// Kernel 2: flash attention over one (b, h, 64-query tile).
// 256 threads. Score phase: 16x16 thread grid, 4x4 scores each.
// Softmax/PV phase: 4 threads per query, 16 output dims each.
// ---------------------------------------------------------------------------
__global__ __launch_bounds__(256) void attn_kernel(
    const float* __restrict__ T,     // [B, S, S]
    const int*   __restrict__ mask,  // [B, 1, S, S]
    const float* __restrict__ alpha_p,
    float*       __restrict__ out)   // [B, S, HID]
{
    extern __shared__ float sm[];
    float* Qt = sm;              // [d][q]  64 x 68  (d-major for float4 reads)
    float* Kt = Qt + 64 * 68;    // [d][k]  64 x 68
    float* Vt = Kt + 64 * 68;    // [k][d]  64 x 68
    float* St = Vt + 64 * 68;    // [q][k]  64 x 68

    const int q0  = blockIdx.x * 64;
    const int h   = blockIdx.y;
    const int b   = blockIdx.z;
    const int tid = threadIdx.x;
    const int tx  = tid & 15;
    const int ty  = tid >> 4;

    const float nalpha = -fabsf(*alpha_p);
    const float* Qg = g_Q + ((size_t)b * NH + h) * S_ * HD;
    const float* Kg = g_K + ((size_t)b * NH + h) * S_ * HD;
    const float* Vg = g_V + ((size_t)b * NH + h) * S_ * HD;
    const float* Tb = T    + (size_t)b * S_ * S_;
    const int*   Mb = mask + (size_t)b * S_ * S_;

    // Load Q tile transposed: Qt[d][q].
    #pragma unroll
    for (int i = 0; i < 16; i++) {
        int idx = tid + i * 256;       // 0..4095
        int qq  = idx >> 6;
        int d   = idx & 63;
        Qt[d * 68 + qq] = Qg[(size_t)(q0 + qq) * HD + d];
    }

    // Online-softmax state: 4 threads per query.
    const int q = tid >> 2;            // 0..63
    const int g = tid & 3;             // 16-dim chunk of the accumulator
    float m_run = -INFINITY;
    float l_run = 0.f;
    float o[16];
    #pragma unroll
    for (int j = 0; j < 16; j++) o[j] = 0.f;

    for (int k0 = 0; k0 < S_; k0 += 64) {
        __syncthreads();   // previous-iteration St/Vt reads complete (also covers Qt load)

        #pragma unroll
        for (int i = 0; i < 16; i++) {
            int idx = tid + i * 256;
            int kk  = idx >> 6;
            int d   = idx & 63;
            Kt[d * 68 + kk]  = Kg[(size_t)(k0 + kk) * HD + d];   // transposed
            Vt[kk * 68 + d]  = Vg[(size_t)(k0 + kk) * HD + d];   // row-major
        }
        __syncthreads();

        // Scores: q rows ty*4..+3, k cols tx*4..+3.
        float sc[4][4] = {};
        #pragma unroll
        for (int d = 0; d < 64; d++) {
            float4 a = *reinterpret_cast<const float4*>(&Qt[d * 68 + ty * 4]);
            float4 k = *reinterpret_cast<const float4*>(&Kt[d * 68 + tx * 4]);
            float av[4] = {a.x, a.y, a.z, a.w};
            float kv[4] = {k.x, k.y, k.z, k.w};
            #pragma unroll
            for (int i = 0; i < 4; i++)
                #pragma unroll
                for (int j = 0; j < 4; j++)
                    sc[i][j] += av[i] * kv[j];
        }

        // Bias + mask, write scores to St.
        #pragma unroll
        for (int i = 0; i < 4; i++) {
            int qg = q0 + ty * 4 + i;
            #pragma unroll
            for (int j = 0; j < 4; j++) {
                int kg = k0 + tx * 4 + j;
                float s = sc[i][j] * 0.125f + nalpha * Tb[(size_t)qg * S_ + kg];
                if (Mb[(size_t)qg * S_ + kg] == 0) s = -1e9f;
                St[(ty * 4 + i) * 68 + (tx * 4 + j)] = s;
            }
        }
        __syncthreads();

        // Online softmax for this tile (4 consecutive lanes own one query).
        float svals[16];
        float mloc = -INFINITY;
        #pragma unroll
        for (int j = 0; j < 16; j++) {
            svals[j] = St[q * 68 + g * 16 + j];
            mloc = fmaxf(mloc, svals[j]);
        }
        mloc = fmaxf(mloc, __shfl_xor_sync(0xFFFFFFFFu, mloc, 1));
        mloc = fmaxf(mloc, __shfl_xor_sync(0xFFFFFFFFu, mloc, 2));
        float m_new = fmaxf(m_run, mloc);
        float corr  = __expf(m_run - m_new);   // 0 on first tile (m_run = -inf)
        float psum  = 0.f;
        #pragma unroll
        for (int j = 0; j < 16; j++) {
            float p = __expf(svals[j] - m_new);
            psum += p;
            St[q * 68 + g * 16 + j] = p;
        }
        psum += __shfl_xor_sync(0xFFFFFFFFu, psum, 1);
        psum += __shfl_xor_sync(0xFFFFFFFFu, psum, 2);
        l_run = l_run * corr + psum;
        m_run = m_new;
        #pragma unroll
        for (int j = 0; j < 16; j++) o[j] *= corr;
        __syncthreads();

        // O += P @ V  (thread: query q, dims g*16 .. g*16+15)
        #pragma unroll 4
        for (int k = 0; k < 64; k++) {
            float p = St[q * 68 + k];
            const float4* vr = reinterpret_cast<const float4*>(&Vt[k * 68 + g * 16]);
            #pragma unroll
            for (int jj = 0; jj < 4; jj++) {
                float4 v = vr[jj];
                o[jj * 4 + 0] += p * v.x;
                o[jj * 4 + 1] += p * v.y;
                o[jj * 4 + 2] += p * v.z;
                o[jj * 4 + 3] += p * v.w;
            }
        }
    }

    // Final normalize + write out[b][q0+q][h*64 + g*16 + j].
    const float inv_l = 1.f / l_run;
    const int s = q0 + q;
    float* op = out + ((size_t)b * S_ + s) * HID + h * HD + g * 16;
    #pragma unroll
    for (int j = 0; j < 16; j++) op[j] = o[j] * inv_l;
}

// ---------------------------------------------------------------------------
// Launch
// ---------------------------------------------------------------------------
extern "C" void kernel_launch(void* const* d_in, const int* in_sizes, int n_in,
                              void* d_out, int out_size)
{
    const float* x     = (const float*)d_in[0];
    const float* T     = (const float*)d_in[1];
    const int*   mask  = (const int*)  d_in[2];
    const float* Wq    = (const float*)d_in[3];
    const float* bq    = (const float*)d_in[4];
    const float* Wk    = (const float*)d_in[5];
    const float* bk    = (const float*)d_in[6];
    const float* Wv    = (const float*)d_in[7];
    const float* bv    = (const float*)d_in[8];
    const float* alpha = (const float*)d_in[9];
    float* out = (float*)d_out;

    // QKV projections: grid (n-tiles, m-tiles, {q,k,v})
    dim3 g1(HID / 64, (B_ * S_) / 64, 3);
    qkv_gemm<<<g1, 256>>>(x, Wq, bq, Wk, bk, Wv, bv);

    // Attention: one block per (64-query tile, head, batch)
    const int smem_bytes = 4 * 64 * 68 * (int)sizeof(float);  // 69632
    cudaFuncSetAttribute(attn_kernel,
                         cudaFuncAttributeMaxDynamicSharedMemorySize, smem_bytes);
    dim3 g2(S_ / 64, NH, B_);
    attn_kernel<<<g2, 256, smem_bytes>>>(T, mask, alpha, out);
}

// round 2
// speedup vs baseline: 3.0648x; 3.0648x over previous
#include <cuda_runtime.h>
#include <math.h>

#define B_  4
#define S_  2048
#define HID 1024
#define NH  16
#define HD  64

typedef unsigned long long u64;

// Scratch (device globals: no allocation allowed in kernel_launch).
__device__ __align__(128) float g_Q[B_ * NH * S_ * HD];
__device__ __align__(128) float g_K[B_ * NH * S_ * HD];
__device__ __align__(128) float g_V[B_ * NH * S_ * HD];
__device__ __align__(128) float g_Wt[3 * HID * HID];   // W transposed: [n][k]

// ---- packed f32x2 helpers -------------------------------------------------
__device__ __forceinline__ void ffma2(u64& acc, u64 a, u64 b) {
    asm("fma.rn.f32x2 %0, %1, %2, %0;" : "+l"(acc) : "l"(a), "l"(b));
}
__device__ __forceinline__ u64 mul2(u64 a, u64 b) {
    u64 r; asm("mul.rn.f32x2 %0, %1, %2;" : "=l"(r) : "l"(a), "l"(b)); return r;
}
__device__ __forceinline__ u64 dup2(float f) {
    u64 r; unsigned u = __float_as_uint(f);
    asm("mov.b64 %0, {%1, %1};" : "=l"(r) : "r"(u)); return r;
}
__device__ __forceinline__ float2 unpk(u64 a) {
    unsigned lo, hi;
    asm("mov.b64 {%0, %1}, %2;" : "=r"(lo), "=r"(hi) : "l"(a));
    return make_float2(__uint_as_float(lo), __uint_as_float(hi));
}
// XOR-swizzled 64-float row layout: float index of 4-float chunk start.
__device__ __forceinline__ int swz(int row, int chunk) {
    return row * 64 + ((chunk ^ ((row >> 2) & 7)) << 2);
}

// ---------------------------------------------------------------------------
// Kernel 0: transpose W -> g_Wt  (Wt[n][k] = W[k][n])
// ---------------------------------------------------------------------------
__global__ __launch_bounds__(256) void transpose_w(
    const float* __restrict__ Wq, const float* __restrict__ Wk,
    const float* __restrict__ Wv)
{
    const float* W = (blockIdx.z == 0) ? Wq : (blockIdx.z == 1) ? Wk : Wv;
    float* D = g_Wt + (size_t)blockIdx.z * HID * HID;
    __shared__ float t[32][33];
    int x0 = blockIdx.x * 32, y0 = blockIdx.y * 32;
    int tx = threadIdx.x & 31, ry = threadIdx.x >> 5;   // 32 x 8
    #pragma unroll
    for (int i = 0; i < 32; i += 8)
        t[ry + i][tx] = W[(size_t)(y0 + ry + i) * HID + x0 + tx];
    __syncthreads();
    #pragma unroll
    for (int i = 0; i < 32; i += 8)
        D[(size_t)(x0 + ry + i) * HID + y0 + tx] = t[tx][ry + i];
}

// ---------------------------------------------------------------------------
// Kernel 1: y = x @ W + b, dot-product oriented (both operands k-contiguous),
// scattered into [B, H, S, D]. 64x64 tile, 256 threads, 4x4 microtile, FFMA2.
// ---------------------------------------------------------------------------
__global__ __launch_bounds__(256, 2) void qkv_gemm(
    const float* __restrict__ x,
    const float* __restrict__ bq, const float* __restrict__ bk,
    const float* __restrict__ bv)
{
    const int z = blockIdx.z;
    const float* Wt   = g_Wt + (size_t)z * HID * HID;
    const float* bias = (z == 0) ? bq : (z == 1) ? bk : bv;
    float* dst        = (z == 0) ? g_Q : (z == 1) ? g_K : g_V;

    __shared__ __align__(16) float xs[64 * 64];
    __shared__ __align__(16) float ws[64 * 64];

    const int m0 = blockIdx.y * 64;
    const int n0 = blockIdx.x * 64;
    const int tid = threadIdx.x;
    const int tx = tid & 15;
    const int ty = tid >> 4;

    u64 acc2[4][4] = {};

    for (int k0 = 0; k0 < HID; k0 += 64) {
        #pragma unroll
        for (int i = 0; i < 4; i++) {
            int lin = tid + i * 256;
            int row = lin >> 4, c = lin & 15;
            *(float4*)&xs[swz(row, c)] =
                *(const float4*)&x[(size_t)(m0 + row) * HID + k0 + c * 4];
            *(float4*)&ws[swz(row, c)] =
                *(const float4*)&Wt[(size_t)(n0 + row) * HID + k0 + c * 4];
        }
        __syncthreads();

        #pragma unroll
        for (int c = 0; c < 16; c++) {
            ulonglong2 a[4], w[4];
            #pragma unroll
            for (int i = 0; i < 4; i++)
                a[i] = *(const ulonglong2*)&xs[swz(ty * 4 + i, c)];
            #pragma unroll
            for (int j = 0; j < 4; j++)
                w[j] = *(const ulonglong2*)&ws[swz(tx * 4 + j, c)];
            #pragma unroll
            for (int i = 0; i < 4; i++)
                #pragma unroll
                for (int j = 0; j < 4; j++) {
                    ffma2(acc2[i][j], a[i].x, w[j].x);
                    ffma2(acc2[i][j], a[i].y, w[j].y);
                }
        }
        __syncthreads();
    }

    const int h = n0 >> 6;   // 64-wide n tile == one head
    #pragma unroll
    for (int i = 0; i < 4; i++) {
        int m = m0 + ty * 4 + i;
        int b = m >> 11;
        int s = m & (S_ - 1);
        float4 r;
        float2 v0 = unpk(acc2[i][0]);
        float2 v1 = unpk(acc2[i][1]);
        float2 v2 = unpk(acc2[i][2]);
        float2 v3 = unpk(acc2[i][3]);
        r.x = v0.x + v0.y + bias[n0 + tx * 4 + 0];
        r.y = v1.x + v1.y + bias[n0 + tx * 4 + 1];
        r.z = v2.x + v2.y + bias[n0 + tx * 4 + 2];
        r.w = v3.x + v3.y + bias[n0 + tx * 4 + 3];
        *(float4*)&dst[(((size_t)b * NH + h) * S_ + s) * HD + tx * 4] = r;
    }
}

// ---------------------------------------------------------------------------
// Kernel 2: flash attention, one (b, h, 64-query tile) per block.
// 256 threads = 16x16 grid, 4x4 microtiles, all-register online softmax.
// ---------------------------------------------------------------------------
__global__ __launch_bounds__(256, 2) void attn_kernel(
    const float* __restrict__ T,
    const int*   __restrict__ mask,
    const float* __restrict__ alpha_p,
    float*       __restrict__ out)
{
    __shared__ __align__(16) float Qs[64 * 64];
    __shared__ __align__(16) float Ks[64 * 64];
    __shared__ __align__(16) float Vs[64 * 64];
    __shared__ __align__(16) float Ps[64 * 64];

    const int q0 = blockIdx.x * 64;
    const int h  = blockIdx.y;
    const int b  = blockIdx.z;
    const int tid = threadIdx.x;
    const int tx = tid & 15;
    const int ty = tid >> 4;

    const float nalpha = -fabsf(*alpha_p);
    const float* Qg = g_Q + ((size_t)b * NH + h) * S_ * HD;
    const float* Kg = g_K + ((size_t)b * NH + h) * S_ * HD;
    const float* Vg = g_V + ((size_t)b * NH + h) * S_ * HD;
    const float* Tb = T    + (size_t)b * S_ * S_;
    const int*   Mb = mask + (size_t)b * S_ * S_;

    #pragma unroll
    for (int i = 0; i < 4; i++) {
        int lin = tid + i * 256;
        int row = lin >> 4, c = lin & 15;
        *(float4*)&Qs[swz(row, c)] =
            *(const float4*)&Qg[(size_t)(q0 + row) * HD + c * 4];
    }

    float m_run[4], l_run[4];
    u64 o2[4][2];
    #pragma unroll
    for (int i = 0; i < 4; i++) {
        m_run[i] = -INFINITY; l_run[i] = 0.f;
        o2[i][0] = 0ull; o2[i][1] = 0ull;
    }

    for (int k0 = 0; k0 < S_; k0 += 64) {
        __syncthreads();   // prior-tile Ks/Vs/Ps reads complete (covers Qs load too)
        #pragma unroll
        for (int i = 0; i < 4; i++) {
            int lin = tid + i * 256;
            int row = lin >> 4, c = lin & 15;
            *(float4*)&Ks[swz(row, c)] =
                *(const float4*)&Kg[(size_t)(k0 + row) * HD + c * 4];
            *(float4*)&Vs[swz(row, c)] =
                *(const float4*)&Vg[(size_t)(k0 + row) * HD + c * 4];
        }
        __syncthreads();

        // ---- scores: 4x4 dot products over d, packed pairs ----
        u64 acc2[4][4] = {};
        #pragma unroll
        for (int c = 0; c < 16; c++) {
            ulonglong2 qa[4], kb[4];
            #pragma unroll
            for (int i = 0; i < 4; i++)
                qa[i] = *(const ulonglong2*)&Qs[swz(ty * 4 + i, c)];
            #pragma unroll
            for (int j = 0; j < 4; j++)
                kb[j] = *(const ulonglong2*)&Ks[swz(tx * 4 + j, c)];
            #pragma unroll
            for (int i = 0; i < 4; i++)
                #pragma unroll
                for (int j = 0; j < 4; j++) {
                    ffma2(acc2[i][j], qa[i].x, kb[j].x);
                    ffma2(acc2[i][j], qa[i].y, kb[j].y);
                }
        }

        // ---- bias + mask + online softmax (registers + shfl) ----
        float p[4][4];
        #pragma unroll
        for (int i = 0; i < 4; i++) {
            int qg = q0 + ty * 4 + i;
            float4 t4 = *(const float4*)&Tb[(size_t)qg * S_ + k0 + tx * 4];
            int4   m4 = *(const int4*)  &Mb[(size_t)qg * S_ + k0 + tx * 4];
            float2 u0 = unpk(acc2[i][0]);
            float2 u1 = unpk(acc2[i][1]);
            float2 u2 = unpk(acc2[i][2]);
            float2 u3 = unpk(acc2[i][3]);
            p[i][0] = (m4.x == 0) ? -1e9f : (u0.x + u0.y) * 0.125f + nalpha * t4.x;
            p[i][1] = (m4.y == 0) ? -1e9f : (u1.x + u1.y) * 0.125f + nalpha * t4.y;
            p[i][2] = (m4.z == 0) ? -1e9f : (u2.x + u2.y) * 0.125f + nalpha * t4.z;
            p[i][3] = (m4.w == 0) ? -1e9f : (u3.x + u3.y) * 0.125f + nalpha * t4.w;
        }

        #pragma unroll
        for (int i = 0; i < 4; i++) {
            float mloc = fmaxf(fmaxf(p[i][0], p[i][1]), fmaxf(p[i][2], p[i][3]));
            mloc = fmaxf(mloc, __shfl_xor_sync(0xFFFFFFFFu, mloc, 1));
            mloc = fmaxf(mloc, __shfl_xor_sync(0xFFFFFFFFu, mloc, 2));
            mloc = fmaxf(mloc, __shfl_xor_sync(0xFFFFFFFFu, mloc, 4));
            mloc = fmaxf(mloc, __shfl_xor_sync(0xFFFFFFFFu, mloc, 8));
            float mnew = fmaxf(m_run[i], mloc);
            float corr = __expf(m_run[i] - mnew);     // 0 on first tile
            float ps = 0.f;
            #pragma unroll
            for (int j = 0; j < 4; j++) {
                p[i][j] = __expf(p[i][j] - mnew);
                ps += p[i][j];
            }
            ps += __shfl_xor_sync(0xFFFFFFFFu, ps, 1);
            ps += __shfl_xor_sync(0xFFFFFFFFu, ps, 2);
            ps += __shfl_xor_sync(0xFFFFFFFFu, ps, 4);
            ps += __shfl_xor_sync(0xFFFFFFFFu, ps, 8);
            l_run[i] = l_run[i] * corr + ps;
            m_run[i] = mnew;
            u64 c2 = dup2(corr);
            o2[i][0] = mul2(o2[i][0], c2);
            o2[i][1] = mul2(o2[i][1], c2);
            *(float4*)&Ps[swz(ty * 4 + i, tx)] =
                make_float4(p[i][0], p[i][1], p[i][2], p[i][3]);
        }
        __syncwarp();   // Ps produced/consumed inside the same 16-lane groups' warp

        // ---- O += P @ V : 4q x 4d microtile, packed pairs over d ----
        #pragma unroll
        for (int kc = 0; kc < 16; kc++) {
            float4 pv[4];
            ulonglong2 vv[4];
            #pragma unroll
            for (int i = 0; i < 4; i++)
                pv[i] = *(const float4*)&Ps[swz(ty * 4 + i, kc)];
            #pragma unroll
            for (int jj = 0; jj < 4; jj++)
                vv[jj] = *(const ulonglong2*)&Vs[swz(kc * 4 + jj, tx)];
            #pragma unroll
            for (int i = 0; i < 4; i++) {
                float pe[4] = {pv[i].x, pv[i].y, pv[i].z, pv[i].w};
                #pragma unroll
                for (int jj = 0; jj < 4; jj++) {
                    u64 pd = dup2(pe[jj]);
                    ffma2(o2[i][0], pd, vv[jj].x);
                    ffma2(o2[i][1], pd, vv[jj].y);
                }
            }
        }
    }

    // ---- epilogue ----
    #pragma unroll
    for (int i = 0; i < 4; i++) {
        float inv = 1.f / l_run[i];
        float2 a = unpk(o2[i][0]);
        float2 c = unpk(o2[i][1]);
        int s = q0 + ty * 4 + i;
        *(float4*)&out[((size_t)b * S_ + s) * HID + h * HD + tx * 4] =
            make_float4(a.x * inv, a.y * inv, c.x * inv, c.y * inv);
    }
}

// ---------------------------------------------------------------------------
// Launch
// ---------------------------------------------------------------------------
extern "C" void kernel_launch(void* const* d_in, const int* in_sizes, int n_in,
                              void* d_out, int out_size)
{
    const float* x     = (const float*)d_in[0];
    const float* T     = (const float*)d_in[1];
    const int*   mask  = (const int*)  d_in[2];
    const float* Wq    = (const float*)d_in[3];
    const float* bq    = (const float*)d_in[4];
    const float* Wk    = (const float*)d_in[5];
    const float* bk    = (const float*)d_in[6];
    const float* Wv    = (const float*)d_in[7];
    const float* bv    = (const float*)d_in[8];
    const float* alpha = (const float*)d_in[9];
    float* out = (float*)d_out;

    dim3 gt(HID / 32, HID / 32, 3);
    transpose_w<<<gt, 256>>>(Wq, Wk, Wv);

    dim3 g1(HID / 64, (B_ * S_) / 64, 3);
    qkv_gemm<<<g1, 256>>>(x, bq, bk, bv);

    dim3 g2(S_ / 64, NH, B_);
    attn_kernel<<<g2, 256>>>(T, mask, alpha, out);
}